// round 1
// baseline (speedup 1.0000x reference)
#include <cuda_runtime.h>
#include <math.h>

#define BSZ   256
#define ISIZE 256
#define HSIZE 512
#define BH    (BSZ*HSIZE)

// Scratch (device globals: no allocation allowed in kernel_launch)
__device__ __align__(16) float g_pre[4*BH];   // f, i, o, c preactivations
__device__ __align__(16) float g_hred[BH];    // sum_h h0*hebb
__device__ __align__(16) float g_its[BH];     // inputstocell
__device__ __align__(16) float g_m[BSZ];      // modulation scalar per batch

// ---------------------------------------------------------------------------
// Kernel 1: hred[b,k] = sum_h h0[b,h] * hebb[b,h,k]   (reads 268MB, HBM-bound)
// grid (B, 2), 256 threads: block handles half the k range for one b.
// ---------------------------------------------------------------------------
__global__ void k_hebb_reduce(const float* __restrict__ h0,
                              const float* __restrict__ hebb)
{
    int b = blockIdx.x;
    int k = blockIdx.y * 256 + threadIdx.x;
    __shared__ float sh0[HSIZE];
    const float* h0b = h0 + b * HSIZE;
    for (int i = threadIdx.x; i < HSIZE; i += 256) sh0[i] = h0b[i];
    __syncthreads();
    const float* hb = hebb + (size_t)b * HSIZE * HSIZE + k;
    float acc = 0.f;
#pragma unroll 8
    for (int h = 0; h < HSIZE; ++h)
        acc = fmaf(sh0[h], hb[(size_t)h * HSIZE], acc);
    g_hred[b * HSIZE + k] = acc;
}

// ---------------------------------------------------------------------------
// Kernel 2: fused gate GEMMs. gate z: 0=f 1=i 2=o 3=c.
//   pre[z][b,k] = x[b,:].Wx_z[k,:]  +  h0[b,:].Wh_z[k,:]
// gate 3 h-side uses plain w with TRANSPOSED access (h0 @ w, not w^T).
// Tiled smem GEMM: BM=BN=64, BK=16, 256 threads, 4x4 per thread.
// ---------------------------------------------------------------------------
#define BM 64
#define BN 64
#define BK 16

__global__ void k_gates(const float* __restrict__ x, const float* __restrict__ h0,
                        const float* __restrict__ x2f, const float* __restrict__ x2i,
                        const float* __restrict__ x2o, const float* __restrict__ x2c,
                        const float* __restrict__ h2f, const float* __restrict__ h2i,
                        const float* __restrict__ h2o, const float* __restrict__ w)
{
    int gate = blockIdx.z;
    int bn0 = blockIdx.x * BN;   // k offset
    int bm0 = blockIdx.y * BM;   // b offset
    __shared__ float As[BM][BK + 1];
    __shared__ float Ws[BN][BK + 1];
    int tid = threadIdx.x;
    int tx = tid & 15, ty = tid >> 4;
    float acc[4][4] = {};

    const float* xw = (gate == 0) ? x2f : (gate == 1) ? x2i : (gate == 2) ? x2o : x2c;
    const float* hw = (gate == 0) ? h2f : (gate == 1) ? h2i : (gate == 2) ? h2o : w;

    for (int phase = 0; phase < 2; ++phase) {
        const float* A = phase ? h0 : x;
        int K = phase ? HSIZE : ISIZE;
        const float* W = phase ? hw : xw;
        bool trans = (phase == 1) && (gate == 3);  // w is [h,k]: transposed access
        for (int k0 = 0; k0 < K; k0 += BK) {
#pragma unroll
            for (int l = 0; l < 4; l++) {
                int e = tid + l * 256; int r = e >> 4; int c = e & 15;
                As[r][c] = A[(size_t)(bm0 + r) * K + k0 + c];
            }
#pragma unroll
            for (int l = 0; l < 4; l++) {
                int e = tid + l * 256; int r = e >> 4; int c = e & 15;
                Ws[r][c] = trans ? W[(size_t)(k0 + c) * HSIZE + bn0 + r]
                                 : W[(size_t)(bn0 + r) * K + k0 + c];
            }
            __syncthreads();
#pragma unroll
            for (int kb = 0; kb < BK; kb++) {
                float ra[4], rb[4];
#pragma unroll
                for (int i = 0; i < 4; i++) ra[i] = As[ty * 4 + i][kb];
#pragma unroll
                for (int j = 0; j < 4; j++) rb[j] = Ws[tx * 4 + j][kb];
#pragma unroll
                for (int i = 0; i < 4; i++)
#pragma unroll
                    for (int j = 0; j < 4; j++)
                        acc[i][j] = fmaf(ra[i], rb[j], acc[i][j]);
            }
            __syncthreads();
        }
    }
    float* out = g_pre + (size_t)gate * BH;
#pragma unroll
    for (int i = 0; i < 4; i++) {
        int bb = bm0 + ty * 4 + i;
#pragma unroll
        for (int j = 0; j < 4; j++) {
            int kk = bn0 + tx * 4 + j;
            out[(size_t)bb * HSIZE + kk] = acc[i][j];
        }
    }
}

// ---------------------------------------------------------------------------
// Kernel 3: gates -> its, cell, hactiv (elementwise over B*H)
// ---------------------------------------------------------------------------
__global__ void k_cell(const float* __restrict__ c0,
                       const float* __restrict__ x2f_b, const float* __restrict__ h2f_b,
                       const float* __restrict__ x2i_b, const float* __restrict__ h2i_b,
                       const float* __restrict__ x2o_b, const float* __restrict__ h2o_b,
                       const float* __restrict__ x2c_b, const float* __restrict__ alpha,
                       float* __restrict__ out_hactiv, float* __restrict__ out_cell)
{
    int idx = blockIdx.x * 256 + threadIdx.x;
    int k = idx & (HSIZE - 1);
    float pf = g_pre[idx]          + x2f_b[k] + h2f_b[k];
    float pi = g_pre[BH + idx]     + x2i_b[k] + h2i_b[k];
    float po = g_pre[2 * BH + idx] + x2o_b[k] + h2o_b[k];
    float pc = g_pre[3 * BH + idx] + x2c_b[k] + alpha[k] * g_hred[idx];
    float fgt = 1.f / (1.f + expf(-pf));
    float ipt = 1.f / (1.f + expf(-pi));
    float opt = 1.f / (1.f + expf(-po));
    float its = tanhf(pc);
    float cell = fgt * c0[idx] + ipt * its;
    float hact = opt * tanhf(cell);
    g_its[idx] = its;
    out_cell[idx] = cell;
    out_hactiv[idx] = hact;
}

// ---------------------------------------------------------------------------
// Kernel 4: m[b] = tanh( hactiv[b,:].h2mod_w + h2mod_b ), one block per b
// ---------------------------------------------------------------------------
__global__ void k_mod(const float* __restrict__ hactiv,
                      const float* __restrict__ h2mod_w,
                      const float* __restrict__ h2mod_b)
{
    int b = blockIdx.x;
    float s = 0.f;
    for (int k = threadIdx.x; k < HSIZE; k += 128)
        s = fmaf(hactiv[b * HSIZE + k], h2mod_w[k], s);
    __shared__ float red[4];
#pragma unroll
    for (int o = 16; o > 0; o >>= 1) s += __shfl_down_sync(0xffffffffu, s, o);
    if ((threadIdx.x & 31) == 0) red[threadIdx.x >> 5] = s;
    __syncthreads();
    if (threadIdx.x == 0)
        g_m[b] = tanhf(red[0] + red[1] + red[2] + red[3] + h2mod_b[0]);
}

// ---------------------------------------------------------------------------
// Kernel 5: hebb_new[b,h,k] = clip(hebb + (m[b]*mfw[k]+mfb[k]) * h0[b,h]*its[b,k])
// float4 over 67M elements: 268MB read + 268MB write, HBM-bound.
// ---------------------------------------------------------------------------
__global__ void k_hebb_update(const float4* __restrict__ hebb4,
                              const float* __restrict__ h0,
                              const float4* __restrict__ mfw4,
                              const float4* __restrict__ mfb4,
                              float4* __restrict__ out4)
{
    int idx = blockIdx.x * 256 + threadIdx.x;     // over B*H*H/4
    int k4 = idx & (HSIZE / 4 - 1);               // 0..127
    int bh = idx >> 7;                            // b*H + h
    int b = bh >> 9;
    float m = g_m[b];
    float s = h0[bh];
    float4 ew = mfw4[k4];
    float4 eb = mfb4[k4];
    const float4* itsp = reinterpret_cast<const float4*>(g_its);
    float4 it = itsp[(b << 7) + k4];
    float4 hv = hebb4[idx];
    float v;
    v = hv.x + (fmaf(m, ew.x, eb.x)) * s * it.x; hv.x = fminf(fmaxf(v, -2.f), 2.f);
    v = hv.y + (fmaf(m, ew.y, eb.y)) * s * it.y; hv.y = fminf(fmaxf(v, -2.f), 2.f);
    v = hv.z + (fmaf(m, ew.z, eb.z)) * s * it.z; hv.z = fminf(fmaxf(v, -2.f), 2.f);
    v = hv.w + (fmaf(m, ew.w, eb.w)) * s * it.w; hv.w = fminf(fmaxf(v, -2.f), 2.f);
    out4[idx] = hv;
}

// ---------------------------------------------------------------------------
extern "C" void kernel_launch(void* const* d_in, const int* in_sizes, int n_in,
                              void* d_out, int out_size)
{
    const float* inputs  = (const float*)d_in[0];
    const float* h0      = (const float*)d_in[1];
    const float* c0      = (const float*)d_in[2];
    const float* hebb    = (const float*)d_in[3];
    const float* w       = (const float*)d_in[4];
    const float* alpha   = (const float*)d_in[5];
    const float* h2f_w   = (const float*)d_in[6];
    const float* h2f_b   = (const float*)d_in[7];
    const float* h2i_w   = (const float*)d_in[8];
    const float* h2i_b   = (const float*)d_in[9];
    const float* h2o_w   = (const float*)d_in[10];
    const float* h2o_b   = (const float*)d_in[11];
    const float* x2f_w   = (const float*)d_in[12];
    const float* x2f_b   = (const float*)d_in[13];
    const float* x2i_w   = (const float*)d_in[14];
    const float* x2i_b   = (const float*)d_in[15];
    const float* x2o_w   = (const float*)d_in[16];
    const float* x2o_b   = (const float*)d_in[17];
    const float* x2c_w   = (const float*)d_in[18];
    const float* x2c_b   = (const float*)d_in[19];
    const float* h2mod_w = (const float*)d_in[20];
    const float* h2mod_b = (const float*)d_in[21];
    const float* mfw     = (const float*)d_in[22];
    const float* mfb     = (const float*)d_in[23];

    float* out       = (float*)d_out;
    float* out_hact  = out;              // [B,H]
    float* out_cell  = out + BH;         // [B,H]
    float* out_hebb  = out + 2 * BH;     // [B,H,H]

    // 1) hebb reduction (independent of gates GEMM)
    dim3 g1(BSZ, 2);
    k_hebb_reduce<<<g1, 256>>>(h0, hebb);

    // 2) gate GEMMs
    dim3 g2(HSIZE / BN, BSZ / BM, 4);
    k_gates<<<g2, 256>>>(inputs, h0, x2f_w, x2i_w, x2o_w, x2c_w,
                         h2f_w, h2i_w, h2o_w, w);

    // 3) elementwise cell/hactiv/its
    k_cell<<<BH / 256, 256>>>(c0, x2f_b, h2f_b, x2i_b, h2i_b, x2o_b, h2o_b,
                              x2c_b, alpha, out_hact, out_cell);

    // 4) modulation scalar
    k_mod<<<BSZ, 128>>>(out_hact, h2mod_w, h2mod_b);

    // 5) hebb update
    int n4 = BSZ * HSIZE * HSIZE / 4;
    k_hebb_update<<<n4 / 256, 256>>>((const float4*)hebb, h0,
                                     (const float4*)mfw, (const float4*)mfb,
                                     (float4*)out_hebb);
}

// round 2
// speedup vs baseline: 1.0020x; 1.0020x over previous
#include <cuda_runtime.h>
#include <math.h>

#define BSZ   256
#define ISIZE 256
#define HSIZE 512
#define BH    (BSZ*HSIZE)
#define RCACHE 48           // hebb rows cached in smem per CTA (96KB)

// Scratch (device globals: no allocation allowed)
__device__ __align__(16) float g_pre[4*BH];   // f, i, o, c preactivations

// ---------------------------------------------------------------------------
// Kernel A: fused gate GEMMs. gate z: 0=f 1=i 2=o 3=c.
//   pre[z][b,k] = x[b,:].Wx_z[k,:]  +  h0[b,:].Wh_z[k,:]
// gate 3 h-side uses plain w with TRANSPOSED access (h0 @ w).
// kb-major smem tiles + LDS.128 in the inner loop (smem-crossbar relief).
// ---------------------------------------------------------------------------
#define BM 64
#define BN 64
#define BK 16

__global__ __launch_bounds__(256)
void k_gates(const float* __restrict__ x, const float* __restrict__ h0,
             const float* __restrict__ x2f, const float* __restrict__ x2i,
             const float* __restrict__ x2o, const float* __restrict__ x2c,
             const float* __restrict__ h2f, const float* __restrict__ h2i,
             const float* __restrict__ h2o, const float* __restrict__ w)
{
    int gate = blockIdx.z;
    int bn0 = blockIdx.x * BN;   // k offset
    int bm0 = blockIdx.y * BM;   // b offset
    __shared__ __align__(16) float As[BK][BM + 4];   // [kb][row]
    __shared__ __align__(16) float Ws[BK][BN + 4];   // [kb][col]
    int tid = threadIdx.x;
    int tx = tid & 15, ty = tid >> 4;
    float acc[4][4] = {};

    const float* xw = (gate == 0) ? x2f : (gate == 1) ? x2i : (gate == 2) ? x2o : x2c;
    const float* hw = (gate == 0) ? h2f : (gate == 1) ? h2i : (gate == 2) ? h2o : w;

    for (int phase = 0; phase < 2; ++phase) {
        const float* A = phase ? h0 : x;
        int K = phase ? HSIZE : ISIZE;
        const float* W = phase ? hw : xw;
        bool trans = (phase == 1) && (gate == 3);  // w is [h,k]
        for (int k0 = 0; k0 < K; k0 += BK) {
#pragma unroll
            for (int l = 0; l < 4; l++) {
                int e = tid + l * 256; int r = e >> 4; int c = e & 15;
                As[c][r] = A[(size_t)(bm0 + r) * K + k0 + c];
            }
            if (trans) {
#pragma unroll
                for (int l = 0; l < 4; l++) {
                    int e = tid + l * 256; int r = e & 63; int c = e >> 6;
                    Ws[c][r] = W[(size_t)(k0 + c) * HSIZE + bn0 + r];  // coalesced
                }
            } else {
#pragma unroll
                for (int l = 0; l < 4; l++) {
                    int e = tid + l * 256; int r = e >> 4; int c = e & 15;
                    Ws[c][r] = W[(size_t)(bn0 + r) * K + k0 + c];
                }
            }
            __syncthreads();
#pragma unroll
            for (int kb = 0; kb < BK; kb++) {
                float4 ra = *(const float4*)&As[kb][ty * 4];
                float4 rb = *(const float4*)&Ws[kb][tx * 4];
                float a[4] = {ra.x, ra.y, ra.z, ra.w};
                float bv[4] = {rb.x, rb.y, rb.z, rb.w};
#pragma unroll
                for (int i = 0; i < 4; i++)
#pragma unroll
                    for (int j = 0; j < 4; j++)
                        acc[i][j] = fmaf(a[i], bv[j], acc[i][j]);
            }
            __syncthreads();
        }
    }
    float* out = g_pre + (size_t)gate * BH;
#pragma unroll
    for (int i = 0; i < 4; i++) {
        int bb = bm0 + ty * 4 + i;
#pragma unroll
        for (int j = 0; j < 4; j++) {
            int kk = bn0 + tx * 4 + j;
            out[(size_t)bb * HSIZE + kk] = acc[i][j];
        }
    }
}

// ---------------------------------------------------------------------------
// Kernel B: fully fused per-batch pipeline. One CTA per b, 512 threads,
// thread t owns column k=t.
//   phase 1: hred[k] = sum_h h0[h]*hebb[b,h,k]; last RCACHE rows -> smem
//   phase 2: gates -> its, cell, hactiv; block-reduce -> m
//   phase 3: hebb update, rows in REVERSE order (L2 reuse), cached rows free
// ---------------------------------------------------------------------------
__global__ __launch_bounds__(HSIZE)
void k_fused(const float* __restrict__ h0, const float* __restrict__ c0,
             const float* __restrict__ hebb,
             const float* __restrict__ alpha,
             const float* __restrict__ x2f_b, const float* __restrict__ h2f_b,
             const float* __restrict__ x2i_b, const float* __restrict__ h2i_b,
             const float* __restrict__ x2o_b, const float* __restrict__ h2o_b,
             const float* __restrict__ x2c_b,
             const float* __restrict__ h2mod_w, const float* __restrict__ h2mod_b,
             const float* __restrict__ mfw, const float* __restrict__ mfb,
             float* __restrict__ out_hact, float* __restrict__ out_cell,
             float* __restrict__ out_hebb)
{
    extern __shared__ float cache[];           // [RCACHE][HSIZE]
    __shared__ float sh0[HSIZE];
    __shared__ float sred[16];
    __shared__ float sm;

    int b = blockIdx.x;
    int k = threadIdx.x;

    sh0[k] = h0[b * HSIZE + k];
    __syncthreads();

    const float* hb = hebb + (size_t)b * HSIZE * HSIZE + k;

    // ---- phase 1: reduction over h ----
    float acc = 0.f;
#pragma unroll 8
    for (int h = 0; h < HSIZE - RCACHE; ++h)
        acc = fmaf(sh0[h], hb[(size_t)h * HSIZE], acc);
#pragma unroll 8
    for (int h = HSIZE - RCACHE; h < HSIZE; ++h) {
        float v = hb[(size_t)h * HSIZE];
        cache[(h - (HSIZE - RCACHE)) * HSIZE + k] = v;   // own column, no sync needed
        acc = fmaf(sh0[h], v, acc);
    }

    // ---- phase 2: gates / cell / hactiv ----
    int idx = b * HSIZE + k;
    float pf = g_pre[idx]            + x2f_b[k] + h2f_b[k];
    float pi = g_pre[BH + idx]       + x2i_b[k] + h2i_b[k];
    float po = g_pre[2 * BH + idx]   + x2o_b[k] + h2o_b[k];
    float pc = g_pre[3 * BH + idx]   + x2c_b[k] + alpha[k] * acc;
    float fgt = 1.f / (1.f + expf(-pf));
    float ipt = 1.f / (1.f + expf(-pi));
    float opt = 1.f / (1.f + expf(-po));
    float its = tanhf(pc);
    float cell = fgt * c0[idx] + ipt * its;
    float hact = opt * tanhf(cell);
    out_cell[idx] = cell;
    out_hact[idx] = hact;

    // block reduce: m = tanh(sum_k hact*h2mod_w[k] + h2mod_b)
    float mv = hact * h2mod_w[k];
#pragma unroll
    for (int o = 16; o > 0; o >>= 1) mv += __shfl_down_sync(0xffffffffu, mv, o);
    if ((k & 31) == 0) sred[k >> 5] = mv;
    __syncthreads();
    if (k == 0) {
        float s = 0.f;
#pragma unroll
        for (int i = 0; i < 16; i++) s += sred[i];
        sm = tanhf(s + h2mod_b[0]);
    }
    __syncthreads();
    float m = sm;
    float eta = fmaf(m, mfw[k], mfb[k]);
    float ei = eta * its;

    // ---- phase 3: hebb update, reverse row order ----
    float* ob = out_hebb + (size_t)b * HSIZE * HSIZE + k;
    // cached rows (top RCACHE) straight from smem
#pragma unroll 8
    for (int h = HSIZE - 1; h >= HSIZE - RCACHE; --h) {
        float v = cache[(h - (HSIZE - RCACHE)) * HSIZE + k];
        float t = fmaf(ei * sh0[h], 1.f, v);
        t = v + ei * sh0[h];
        t = fminf(fmaxf(t, -2.f), 2.f);
        ob[(size_t)h * HSIZE] = t;
    }
    // remaining rows from global (reverse order -> L2 hits on recent rows)
#pragma unroll 8
    for (int h = HSIZE - RCACHE - 1; h >= 0; --h) {
        float v = hb[(size_t)h * HSIZE];
        float t = v + ei * sh0[h];
        t = fminf(fmaxf(t, -2.f), 2.f);
        ob[(size_t)h * HSIZE] = t;
    }
}

// ---------------------------------------------------------------------------
extern "C" void kernel_launch(void* const* d_in, const int* in_sizes, int n_in,
                              void* d_out, int out_size)
{
    const float* inputs  = (const float*)d_in[0];
    const float* h0      = (const float*)d_in[1];
    const float* c0      = (const float*)d_in[2];
    const float* hebb    = (const float*)d_in[3];
    const float* w       = (const float*)d_in[4];
    const float* alpha   = (const float*)d_in[5];
    const float* h2f_w   = (const float*)d_in[6];
    const float* h2f_b   = (const float*)d_in[7];
    const float* h2i_w   = (const float*)d_in[8];
    const float* h2i_b   = (const float*)d_in[9];
    const float* h2o_w   = (const float*)d_in[10];
    const float* h2o_b   = (const float*)d_in[11];
    const float* x2f_w   = (const float*)d_in[12];
    const float* x2f_b   = (const float*)d_in[13];
    const float* x2i_w   = (const float*)d_in[14];
    const float* x2i_b   = (const float*)d_in[15];
    const float* x2o_w   = (const float*)d_in[16];
    const float* x2o_b   = (const float*)d_in[17];
    const float* x2c_w   = (const float*)d_in[18];
    const float* x2c_b   = (const float*)d_in[19];
    const float* h2mod_w = (const float*)d_in[20];
    const float* h2mod_b = (const float*)d_in[21];
    const float* mfw     = (const float*)d_in[22];
    const float* mfb     = (const float*)d_in[23];

    float* out       = (float*)d_out;
    float* out_hact  = out;              // [B,H]
    float* out_cell  = out + BH;         // [B,H]
    float* out_hebb  = out + 2 * BH;     // [B,H,H]

    // opt-in to 96KB dynamic smem for the fused kernel (idempotent)
    cudaFuncSetAttribute(k_fused, cudaFuncAttributeMaxDynamicSharedMemorySize,
                         RCACHE * HSIZE * (int)sizeof(float));

    // A) gate GEMMs -> g_pre
    dim3 g2(HSIZE / BN, BSZ / BM, 4);
    k_gates<<<g2, 256>>>(inputs, h0, x2f_w, x2i_w, x2o_w, x2c_w,
                         h2f_w, h2i_w, h2o_w, w);

    // B) fused reduce + cell + mod + hebb update
    k_fused<<<BSZ, HSIZE, RCACHE * HSIZE * sizeof(float)>>>(
        h0, c0, hebb, alpha,
        x2f_b, h2f_b, x2i_b, h2i_b, x2o_b, h2o_b, x2c_b,
        h2mod_w, h2mod_b, mfw, mfb,
        out_hact, out_cell, out_hebb);
}

// round 3
// speedup vs baseline: 1.3284x; 1.3257x over previous
#include <cuda_runtime.h>
#include <math.h>

#define BSZ   256
#define ISIZE 256
#define HSIZE 512
#define BH    (BSZ*HSIZE)

// Scratch (device globals: no allocation allowed)
__device__ __align__(16) float g_pre[4*BH];   // f, i, o, c preactivations
__device__ __align__(16) float g_hred[BH];    // sum_h h0*hebb
__device__ __align__(16) float g_ei[BH];      // eta*its per (b,k)

// ---------------------------------------------------------------------------
// K1: heterogeneous grid.
//  blocks [0,256):   reduce  hred[b,k] = sum_h h0[b,h]*hebb[b,h,k]  (268MB)
//  blocks [256,384): gate GEMMs (4 gates x 8x4 tiles of 64x64), hidden in
//                    the reduce's bandwidth shadow.
// ---------------------------------------------------------------------------
#define BK 16
#define NRED 256

__global__ __launch_bounds__(512)
void k1(const float* __restrict__ x, const float* __restrict__ h0,
        const float* __restrict__ hebb,
        const float* __restrict__ x2f, const float* __restrict__ x2i,
        const float* __restrict__ x2o, const float* __restrict__ x2c,
        const float* __restrict__ h2f, const float* __restrict__ h2i,
        const float* __restrict__ h2o, const float* __restrict__ w)
{
    __shared__ union {
        float sh0[HSIZE];
        struct { float As[BK][64 + 4]; float Ws[BK][64 + 4]; } t;
    } sm;

    int tid = threadIdx.x;

    if (blockIdx.x < NRED) {
        // ---------------- reduce path ----------------
        int b = blockIdx.x;
        int k = tid;
        sm.sh0[k] = h0[b * HSIZE + k];
        __syncthreads();
        const float* hb = hebb + (size_t)b * HSIZE * HSIZE + k;
        float acc = 0.f;
#pragma unroll 8
        for (int h = 0; h < HSIZE; ++h)
            acc = fmaf(sm.sh0[h], hb[(size_t)h * HSIZE], acc);
        g_hred[b * HSIZE + k] = acc;
        return;
    }

    // ---------------- gates path ----------------
    int g = blockIdx.x - NRED;          // 0..127
    int gate = g >> 5;                  // 32 CTAs per gate
    int ct = g & 31;
    int bn0 = (ct & 7) * 64;            // k offset
    int bm0 = (ct >> 3) * 64;           // b offset
    int tx = tid & 15, ty = tid >> 4;   // ty: 0..31
    float acc[2][4] = {};

    const float* xw = (gate == 0) ? x2f : (gate == 1) ? x2i : (gate == 2) ? x2o : x2c;
    const float* hw = (gate == 0) ? h2f : (gate == 1) ? h2i : (gate == 2) ? h2o : w;

    for (int phase = 0; phase < 2; ++phase) {
        const float* A = phase ? h0 : x;
        int K = phase ? HSIZE : ISIZE;
        const float* W = phase ? hw : xw;
        bool trans = (phase == 1) && (gate == 3);   // w is [h,k]
        for (int k0 = 0; k0 < K; k0 += BK) {
#pragma unroll
            for (int l = 0; l < 2; l++) {
                int e = tid + l * 512; int r = e >> 4; int c = e & 15;
                sm.t.As[c][r] = A[(size_t)(bm0 + r) * K + k0 + c];
            }
            if (trans) {
#pragma unroll
                for (int l = 0; l < 2; l++) {
                    int e = tid + l * 512; int r = e & 63; int c = e >> 6;
                    sm.t.Ws[c][r] = W[(size_t)(k0 + c) * HSIZE + bn0 + r];
                }
            } else {
#pragma unroll
                for (int l = 0; l < 2; l++) {
                    int e = tid + l * 512; int r = e >> 4; int c = e & 15;
                    sm.t.Ws[c][r] = W[(size_t)(bn0 + r) * K + k0 + c];
                }
            }
            __syncthreads();
#pragma unroll
            for (int kb = 0; kb < BK; kb++) {
                float2 ra = *(const float2*)&sm.t.As[kb][ty * 2];
                float4 rb = *(const float4*)&sm.t.Ws[kb][tx * 4];
                float a[2] = {ra.x, ra.y};
                float bv[4] = {rb.x, rb.y, rb.z, rb.w};
#pragma unroll
                for (int i = 0; i < 2; i++)
#pragma unroll
                    for (int j = 0; j < 4; j++)
                        acc[i][j] = fmaf(a[i], bv[j], acc[i][j]);
            }
            __syncthreads();
        }
    }
    float* out = g_pre + (size_t)gate * BH;
#pragma unroll
    for (int i = 0; i < 2; i++) {
        int bb = bm0 + ty * 2 + i;
#pragma unroll
        for (int j = 0; j < 4; j++)
            out[(size_t)bb * HSIZE + bn0 + tx * 4 + j] = acc[i][j];
    }
}

// ---------------------------------------------------------------------------
// K2: per-batch cell/hactiv + modulation scalar + ei = (m*mfw+mfb)*its.
// One CTA per b, 512 threads (thread = column k). Tiny (few MB traffic).
// ---------------------------------------------------------------------------
__global__ __launch_bounds__(HSIZE)
void k2(const float* __restrict__ c0, const float* __restrict__ alpha,
        const float* __restrict__ x2f_b, const float* __restrict__ h2f_b,
        const float* __restrict__ x2i_b, const float* __restrict__ h2i_b,
        const float* __restrict__ x2o_b, const float* __restrict__ h2o_b,
        const float* __restrict__ x2c_b,
        const float* __restrict__ h2mod_w, const float* __restrict__ h2mod_b,
        const float* __restrict__ mfw, const float* __restrict__ mfb,
        float* __restrict__ out_hact, float* __restrict__ out_cell)
{
    __shared__ float sred[16];
    __shared__ float smv;
    int b = blockIdx.x;
    int k = threadIdx.x;
    int idx = b * HSIZE + k;

    float pf = g_pre[idx]          + x2f_b[k] + h2f_b[k];
    float pi = g_pre[BH + idx]     + x2i_b[k] + h2i_b[k];
    float po = g_pre[2 * BH + idx] + x2o_b[k] + h2o_b[k];
    float pc = g_pre[3 * BH + idx] + x2c_b[k] + alpha[k] * g_hred[idx];
    float fgt = 1.f / (1.f + expf(-pf));
    float ipt = 1.f / (1.f + expf(-pi));
    float opt = 1.f / (1.f + expf(-po));
    float its = tanhf(pc);
    float cell = fgt * c0[idx] + ipt * its;
    float hact = opt * tanhf(cell);
    out_cell[idx] = cell;
    out_hact[idx] = hact;

    float mv = hact * h2mod_w[k];
#pragma unroll
    for (int o = 16; o > 0; o >>= 1) mv += __shfl_down_sync(0xffffffffu, mv, o);
    if ((k & 31) == 0) sred[k >> 5] = mv;
    __syncthreads();
    if (k == 0) {
        float s = 0.f;
#pragma unroll
        for (int i = 0; i < 16; i++) s += sred[i];
        smv = tanhf(s + h2mod_b[0]);
    }
    __syncthreads();
    float m = smv;
    g_ei[idx] = fmaf(m, mfw[k], mfb[k]) * its;
}

// ---------------------------------------------------------------------------
// K3: hebb_new[b,h,k] = clip(hebb + h0[b,h]*ei[b,k], -2, 2)
// Pure streaming: 268MB R + 268MB W. 4 float4 per thread for ILP.
// ---------------------------------------------------------------------------
__global__ __launch_bounds__(256)
void k3(const float4* __restrict__ hebb4, const float* __restrict__ h0,
        float4* __restrict__ out4)
{
    const float4* ei4 = reinterpret_cast<const float4*>(g_ei);
    int base = blockIdx.x * 1024 + threadIdx.x;
#pragma unroll
    for (int j = 0; j < 4; j++) {
        int idx = base + j * 256;             // over B*H*H/4
        int k4 = idx & 127;
        int bh = idx >> 7;
        int b = bh >> 9;
        float s = h0[bh];
        float4 e = ei4[(b << 7) + k4];
        float4 hv = hebb4[idx];
        float v;
        v = fmaf(s, e.x, hv.x); hv.x = fminf(fmaxf(v, -2.f), 2.f);
        v = fmaf(s, e.y, hv.y); hv.y = fminf(fmaxf(v, -2.f), 2.f);
        v = fmaf(s, e.z, hv.z); hv.z = fminf(fmaxf(v, -2.f), 2.f);
        v = fmaf(s, e.w, hv.w); hv.w = fminf(fmaxf(v, -2.f), 2.f);
        out4[idx] = hv;
    }
}

// ---------------------------------------------------------------------------
extern "C" void kernel_launch(void* const* d_in, const int* in_sizes, int n_in,
                              void* d_out, int out_size)
{
    const float* inputs  = (const float*)d_in[0];
    const float* h0      = (const float*)d_in[1];
    const float* c0      = (const float*)d_in[2];
    const float* hebb    = (const float*)d_in[3];
    const float* w       = (const float*)d_in[4];
    const float* alpha   = (const float*)d_in[5];
    const float* h2f_w   = (const float*)d_in[6];
    const float* h2f_b   = (const float*)d_in[7];
    const float* h2i_w   = (const float*)d_in[8];
    const float* h2i_b   = (const float*)d_in[9];
    const float* h2o_w   = (const float*)d_in[10];
    const float* h2o_b   = (const float*)d_in[11];
    const float* x2f_w   = (const float*)d_in[12];
    const float* x2f_b   = (const float*)d_in[13];
    const float* x2i_w   = (const float*)d_in[14];
    const float* x2i_b   = (const float*)d_in[15];
    const float* x2o_w   = (const float*)d_in[16];
    const float* x2o_b   = (const float*)d_in[17];
    const float* x2c_w   = (const float*)d_in[18];
    const float* x2c_b   = (const float*)d_in[19];
    const float* h2mod_w = (const float*)d_in[20];
    const float* h2mod_b = (const float*)d_in[21];
    const float* mfw     = (const float*)d_in[22];
    const float* mfb     = (const float*)d_in[23];

    float* out       = (float*)d_out;
    float* out_hact  = out;              // [B,H]
    float* out_cell  = out + BH;         // [B,H]
    float* out_hebb  = out + 2 * BH;     // [B,H,H]

    // K1: reduce (256 CTAs) + gate GEMMs (128 CTAs) in one heterogeneous grid
    k1<<<NRED + 128, 512>>>(inputs, h0, hebb,
                            x2f_w, x2i_w, x2o_w, x2c_w,
                            h2f_w, h2i_w, h2o_w, w);

    // K2: cell / hactiv / m / ei
    k2<<<BSZ, HSIZE>>>(c0, alpha, x2f_b, h2f_b, x2i_b, h2i_b, x2o_b, h2o_b,
                       x2c_b, h2mod_w, h2mod_b, mfw, mfb, out_hact, out_cell);

    // K3: hebb update (268MB R + 268MB W streaming)
    int nblk = (BSZ * HSIZE * HSIZE / 4) / 1024;   // 8192
    k3<<<nblk, 256>>>((const float4*)hebb, h0, (float4*)out_hebb);
}

// round 4
// speedup vs baseline: 1.3701x; 1.0314x over previous
#include <cuda_runtime.h>
#include <math.h>

#define BSZ   256
#define ISIZE 256
#define HSIZE 512
#define BH    (BSZ*HSIZE)

#define BK 16
#define NU_GATES 256          // 2 phases x 4 gates x 32 tiles
#define NU_TOTAL (NU_GATES + 512)
#define GRID1 296             // 2 CTAs per SM x 148 SMs

// Scratch (device globals)
__device__ __align__(16) float g_prex[4*BH];   // x-side gate partials
__device__ __align__(16) float g_preh[4*BH];   // h-side gate partials
__device__ __align__(16) float g_hredp[2*BH];  // hred partials (2 h-halves)
__device__ __align__(16) float g_ei[BH];       // eta*its per (b,k)

// ---------------------------------------------------------------------------
// K1: persistent heterogeneous kernel, 296 CTAs x 512 threads.
//  units [0,256):   gate GEMM tiles (phase-split: x-side / h-side)
//  units [256,768): hebb reduce units (b, h-half), float4 streaming
// ---------------------------------------------------------------------------
__global__ __launch_bounds__(512, 2)
void k1(const float* __restrict__ x, const float* __restrict__ h0,
        const float* __restrict__ hebb,
        const float* __restrict__ x2f, const float* __restrict__ x2i,
        const float* __restrict__ x2o, const float* __restrict__ x2c,
        const float* __restrict__ h2f, const float* __restrict__ h2i,
        const float* __restrict__ h2o, const float* __restrict__ w)
{
    __shared__ union {
        struct { float sh0[256]; float4 sp[512]; } r;      // reduce: 9KB
        struct { float As[BK][68]; float Ws[BK][68]; } t;  // gates: 8.7KB
    } sm;

    int tid = threadIdx.x;

    for (int u = blockIdx.x; u < NU_TOTAL; u += GRID1) {
        if (u >= NU_GATES) {
            // ---------------- reduce unit: (b, half) over 256 rows ----------
            int ru = u - NU_GATES;
            int b = ru >> 1;
            int half = ru & 1;
            if (tid < 256) sm.r.sh0[tid] = h0[b * HSIZE + half * 256 + tid];
            __syncthreads();
            int g = tid >> 7, t = tid & 127;     // 4 groups x 64 rows, 128 f4 cols
            const float4* hb4 = (const float4*)(hebb + (size_t)b * HSIZE * HSIZE)
                                + (size_t)(half * 256 + g * 64) * 128 + t;
            const float* s0 = &sm.r.sh0[g * 64];
            float4 acc = make_float4(0.f, 0.f, 0.f, 0.f);
#pragma unroll 8
            for (int h = 0; h < 64; ++h) {
                float s = s0[h];
                float4 v = hb4[(size_t)h * 128];
                acc.x = fmaf(s, v.x, acc.x);
                acc.y = fmaf(s, v.y, acc.y);
                acc.z = fmaf(s, v.z, acc.z);
                acc.w = fmaf(s, v.w, acc.w);
            }
            sm.r.sp[tid] = acc;
            __syncthreads();
            if (tid < 128) {
                float4 a = sm.r.sp[tid];
                float4 b2 = sm.r.sp[128 + tid];
                float4 c = sm.r.sp[256 + tid];
                float4 d = sm.r.sp[384 + tid];
                a.x += b2.x + c.x + d.x;
                a.y += b2.y + c.y + d.y;
                a.z += b2.z + c.z + d.z;
                a.w += b2.w + c.w + d.w;
                ((float4*)(g_hredp + half * BH + b * HSIZE))[tid] = a;
            }
            __syncthreads();
        } else {
            // ---------------- gate GEMM unit ------------------------------
            int phase = u >> 7;            // 0 = x-side, 1 = h-side
            int r = u & 127;
            int gate = r >> 5;
            int ct = r & 31;
            int bn0 = (ct & 7) * 64;       // k offset
            int bm0 = (ct >> 3) * 64;      // b offset
            const float* A = phase ? h0 : x;
            int K = phase ? HSIZE : ISIZE;
            const float* W;
            if (phase == 0)
                W = (gate == 0) ? x2f : (gate == 1) ? x2i : (gate == 2) ? x2o : x2c;
            else
                W = (gate == 0) ? h2f : (gate == 1) ? h2i : (gate == 2) ? h2o : w;
            bool trans = (phase == 1) && (gate == 3);   // w is [h,k]

            int tx = tid & 15, ty = tid >> 4;           // ty: 0..31
            float acc[2][4] = {};

            for (int k0 = 0; k0 < K; k0 += BK) {
#pragma unroll
                for (int l = 0; l < 2; l++) {
                    int e = tid + l * 512; int rr = e >> 4; int cc = e & 15;
                    sm.t.As[cc][rr] = A[(size_t)(bm0 + rr) * K + k0 + cc];
                }
                if (trans) {
#pragma unroll
                    for (int l = 0; l < 2; l++) {
                        int e = tid + l * 512; int rr = e & 63; int cc = e >> 6;
                        sm.t.Ws[cc][rr] = W[(size_t)(k0 + cc) * HSIZE + bn0 + rr];
                    }
                } else {
#pragma unroll
                    for (int l = 0; l < 2; l++) {
                        int e = tid + l * 512; int rr = e >> 4; int cc = e & 15;
                        sm.t.Ws[cc][rr] = W[(size_t)(bn0 + rr) * K + k0 + cc];
                    }
                }
                __syncthreads();
#pragma unroll
                for (int kb = 0; kb < BK; kb++) {
                    float2 ra = *(const float2*)&sm.t.As[kb][ty * 2];
                    float4 rb = *(const float4*)&sm.t.Ws[kb][tx * 4];
                    float a[2] = {ra.x, ra.y};
                    float bv[4] = {rb.x, rb.y, rb.z, rb.w};
#pragma unroll
                    for (int i = 0; i < 2; i++)
#pragma unroll
                        for (int j = 0; j < 4; j++)
                            acc[i][j] = fmaf(a[i], bv[j], acc[i][j]);
                }
                __syncthreads();
            }
            float* outb = (phase ? g_preh : g_prex) + (size_t)gate * BH;
#pragma unroll
            for (int i = 0; i < 2; i++) {
                int bb = bm0 + ty * 2 + i;
#pragma unroll
                for (int j = 0; j < 4; j++)
                    outb[(size_t)bb * HSIZE + bn0 + tx * 4 + j] = acc[i][j];
            }
            // trailing __syncthreads of the last k0 iteration protects smem
        }
    }
}

// ---------------------------------------------------------------------------
// K2: per-batch cell/hactiv + modulation scalar + ei = (m*mfw+mfb)*its.
// ---------------------------------------------------------------------------
__global__ __launch_bounds__(HSIZE)
void k2(const float* __restrict__ c0, const float* __restrict__ alpha,
        const float* __restrict__ x2f_b, const float* __restrict__ h2f_b,
        const float* __restrict__ x2i_b, const float* __restrict__ h2i_b,
        const float* __restrict__ x2o_b, const float* __restrict__ h2o_b,
        const float* __restrict__ x2c_b,
        const float* __restrict__ h2mod_w, const float* __restrict__ h2mod_b,
        const float* __restrict__ mfw, const float* __restrict__ mfb,
        float* __restrict__ out_hact, float* __restrict__ out_cell)
{
    __shared__ float sred[16];
    __shared__ float smv;
    int b = blockIdx.x;
    int k = threadIdx.x;
    int idx = b * HSIZE + k;

    float pf = g_prex[idx]          + g_preh[idx]          + x2f_b[k] + h2f_b[k];
    float pi = g_prex[BH + idx]     + g_preh[BH + idx]     + x2i_b[k] + h2i_b[k];
    float po = g_prex[2 * BH + idx] + g_preh[2 * BH + idx] + x2o_b[k] + h2o_b[k];
    float hred = g_hredp[idx] + g_hredp[BH + idx];
    float pc = g_prex[3 * BH + idx] + g_preh[3 * BH + idx] + x2c_b[k]
             + alpha[k] * hred;
    float fgt = 1.f / (1.f + expf(-pf));
    float ipt = 1.f / (1.f + expf(-pi));
    float opt = 1.f / (1.f + expf(-po));
    float its = tanhf(pc);
    float cell = fgt * c0[idx] + ipt * its;
    float hact = opt * tanhf(cell);
    out_cell[idx] = cell;
    out_hact[idx] = hact;

    float mv = hact * h2mod_w[k];
#pragma unroll
    for (int o = 16; o > 0; o >>= 1) mv += __shfl_down_sync(0xffffffffu, mv, o);
    if ((k & 31) == 0) sred[k >> 5] = mv;
    __syncthreads();
    if (k == 0) {
        float s = 0.f;
#pragma unroll
        for (int i = 0; i < 16; i++) s += sred[i];
        smv = tanhf(s + h2mod_b[0]);
    }
    __syncthreads();
    g_ei[idx] = fmaf(smv, mfw[k], mfb[k]) * its;
}

// ---------------------------------------------------------------------------
// K3: hebb_new[b,h,k] = clip(hebb + h0[b,h]*ei[b,k], -2, 2). Pure streaming.
// ---------------------------------------------------------------------------
__global__ __launch_bounds__(256)
void k3(const float4* __restrict__ hebb4, const float* __restrict__ h0,
        float4* __restrict__ out4)
{
    const float4* ei4 = reinterpret_cast<const float4*>(g_ei);
    int base = blockIdx.x * 1024 + threadIdx.x;
#pragma unroll
    for (int j = 0; j < 4; j++) {
        int idx = base + j * 256;
        int k4 = idx & 127;
        int bh = idx >> 7;
        int b = bh >> 9;
        float s = h0[bh];
        float4 e = ei4[(b << 7) + k4];
        float4 hv = hebb4[idx];
        float v;
        v = fmaf(s, e.x, hv.x); hv.x = fminf(fmaxf(v, -2.f), 2.f);
        v = fmaf(s, e.y, hv.y); hv.y = fminf(fmaxf(v, -2.f), 2.f);
        v = fmaf(s, e.z, hv.z); hv.z = fminf(fmaxf(v, -2.f), 2.f);
        v = fmaf(s, e.w, hv.w); hv.w = fminf(fmaxf(v, -2.f), 2.f);
        out4[idx] = hv;
    }
}

// ---------------------------------------------------------------------------
extern "C" void kernel_launch(void* const* d_in, const int* in_sizes, int n_in,
                              void* d_out, int out_size)
{
    const float* inputs  = (const float*)d_in[0];
    const float* h0      = (const float*)d_in[1];
    const float* c0      = (const float*)d_in[2];
    const float* hebb    = (const float*)d_in[3];
    const float* w       = (const float*)d_in[4];
    const float* alpha   = (const float*)d_in[5];
    const float* h2f_w   = (const float*)d_in[6];
    const float* h2f_b   = (const float*)d_in[7];
    const float* h2i_w   = (const float*)d_in[8];
    const float* h2i_b   = (const float*)d_in[9];
    const float* h2o_w   = (const float*)d_in[10];
    const float* h2o_b   = (const float*)d_in[11];
    const float* x2f_w   = (const float*)d_in[12];
    const float* x2f_b   = (const float*)d_in[13];
    const float* x2i_w   = (const float*)d_in[14];
    const float* x2i_b   = (const float*)d_in[15];
    const float* x2o_w   = (const float*)d_in[16];
    const float* x2o_b   = (const float*)d_in[17];
    const float* x2c_w   = (const float*)d_in[18];
    const float* x2c_b   = (const float*)d_in[19];
    const float* h2mod_w = (const float*)d_in[20];
    const float* h2mod_b = (const float*)d_in[21];
    const float* mfw     = (const float*)d_in[22];
    const float* mfb     = (const float*)d_in[23];

    float* out       = (float*)d_out;
    float* out_hact  = out;              // [B,H]
    float* out_cell  = out + BH;         // [B,H]
    float* out_hebb  = out + 2 * BH;     // [B,H,H]

    // K1: persistent heterogeneous grid (gates + reduce)
    k1<<<GRID1, 512>>>(inputs, h0, hebb,
                       x2f_w, x2i_w, x2o_w, x2c_w,
                       h2f_w, h2i_w, h2o_w, w);

    // K2: cell / hactiv / m / ei
    k2<<<BSZ, HSIZE>>>(c0, alpha, x2f_b, h2f_b, x2i_b, h2i_b, x2o_b, h2o_b,
                       x2c_b, h2mod_w, h2mod_b, mfw, mfb, out_hact, out_cell);

    // K3: hebb update (268MB R + 268MB W streaming)
    int nblk = (BSZ * HSIZE * HSIZE / 4) / 1024;   // 8192
    k3<<<nblk, 256>>>((const float4*)hebb, h0, (float4*)out_hebb);
}